// round 1
// baseline (speedup 1.0000x reference)
#include <cuda_runtime.h>
#include <math.h>
#include <stdint.h>

// Problem constants
#define BB 32
#define SS 1024
#define DMODEL 1024
#define NLABEL 8192
#define DHH 64
#define NHEAD 16
#define MROWS (BB * SS)        // 32768
#define EPS_ 1e-12f

// ---------------- device scratch (static allocation; no cudaMalloc) ----------
__device__ float g_h1[(size_t)MROWS * 2048];   // relu(e@w1+b1)        256MB
__device__ float g_ek[(size_t)MROWS * 1024];   // ek_pre -> ek (inplace) 128MB
__device__ float g_w2f[2048 * 1024];           // folded tc_w2 @ blockdiag(hyp_w)
__device__ float g_b2f[1024];                  // folded bias
__device__ float g_qv[512 * 64];               // final q per (b,head)
__device__ float g_sqq[512];                   // |q|^2 per (b,head)

// ---------------- weight folding: w2f[k][j*64+d'] = sum_d w2[k][j*64+d]*hyp_w[d][d']
__global__ void fold_w2_kernel(const float* __restrict__ tc_w2,
                               const float* __restrict__ hyp_w) {
    __shared__ float hw[64 * 64];
    __shared__ float row[1024];
    int k = blockIdx.x;
    int tid = threadIdx.x;
    for (int i = tid; i < 4096; i += 256) hw[i] = hyp_w[i];
    for (int i = tid; i < 1024; i += 256) row[i] = tc_w2[(size_t)k * 1024 + i];
    __syncthreads();
#pragma unroll
    for (int t = 0; t < 4; t++) {
        int c = tid + t * 256;
        int j = c >> 6, dp = c & 63;
        float acc = 0.f;
#pragma unroll 8
        for (int d = 0; d < 64; d++) acc += row[j * 64 + d] * hw[d * 64 + dp];
        g_w2f[(size_t)k * 1024 + c] = acc;
    }
}

__global__ void fold_b2_kernel(const float* __restrict__ tc_b2,
                               const float* __restrict__ hyp_w,
                               const float* __restrict__ hyp_b) {
    int c = blockIdx.x * 256 + threadIdx.x;
    if (c < 1024) {
        int j = c >> 6, dp = c & 63;
        float acc = hyp_b[dp];
        for (int d = 0; d < 64; d++) acc += tc_b2[j * 64 + d] * hyp_w[d * 64 + dp];
        g_b2f[c] = acc;
    }
}

// ---------------- SGEMM: C[M,N] = op(A[M,K] @ B[K,N] + bias[N]) -------------
// 128x128x8 block tile, 8x8 per-thread microtile, 256 threads
#define BM 128
#define BN 128
#define BK 8
#define TM 8
#define TN 8

template <bool RELU>
__global__ __launch_bounds__(256) void sgemm_kernel(
    const float* __restrict__ A, const float* __restrict__ B,
    const float* __restrict__ bias, float* __restrict__ C,
    int M, int N, int K) {
    __shared__ __align__(16) float As[BK][BM];
    __shared__ __align__(16) float Bs[BK][BN];
    const int tid = threadIdx.x;
    const int bx = blockIdx.x;   // N tile
    const int by = blockIdx.y;   // M tile

    const float* Ablk = A + (size_t)by * BM * K;
    const float* Bblk = B + (size_t)bx * BN;

    const int arow = tid >> 1;           // 0..127
    const int acol = (tid & 1) * 4;      // 0 / 4
    const int brow = tid >> 5;           // 0..7
    const int bcol = (tid & 31) * 4;     // 0..124
    const int ty = (tid >> 4) * TM;      // 0..120
    const int tx = (tid & 15) * TN;      // 0..120

    float acc[TM][TN];
#pragma unroll
    for (int i = 0; i < TM; i++)
#pragma unroll
        for (int j = 0; j < TN; j++) acc[i][j] = 0.f;

    for (int k0 = 0; k0 < K; k0 += BK) {
        float4 av = *(const float4*)(Ablk + (size_t)arow * K + k0 + acol);
        float4 bv = *(const float4*)(Bblk + (size_t)(k0 + brow) * N + bcol);
        As[acol + 0][arow] = av.x;
        As[acol + 1][arow] = av.y;
        As[acol + 2][arow] = av.z;
        As[acol + 3][arow] = av.w;
        *(float4*)(&Bs[brow][bcol]) = bv;
        __syncthreads();
#pragma unroll
        for (int k = 0; k < BK; k++) {
            float ar[TM], br[TN];
            *(float4*)(ar)     = *(const float4*)(&As[k][ty]);
            *(float4*)(ar + 4) = *(const float4*)(&As[k][ty + 4]);
            *(float4*)(br)     = *(const float4*)(&Bs[k][tx]);
            *(float4*)(br + 4) = *(const float4*)(&Bs[k][tx + 4]);
#pragma unroll
            for (int i = 0; i < TM; i++)
#pragma unroll
                for (int j = 0; j < TN; j++) acc[i][j] += ar[i] * br[j];
        }
        __syncthreads();
    }

    const int crow0 = by * BM + ty;
    const int ccol0 = bx * BN + tx;
    float breg[TN];
#pragma unroll
    for (int j = 0; j < TN; j++) breg[j] = bias[ccol0 + j];
#pragma unroll
    for (int i = 0; i < TM; i++) {
        float v[TN];
#pragma unroll
        for (int j = 0; j < TN; j++) {
            float c = acc[i][j] + breg[j];
            if (RELU) c = fmaxf(c, 0.f);
            v[j] = c;
        }
        float* crow = C + (size_t)(crow0 + i) * N + ccol0;
        *(float4*)(crow)     = *(float4*)(v);
        *(float4*)(crow + 4) = *(float4*)(v + 4);
    }
}

// ---------------- expmap0 in-place over g_ek, one warp per 64-vector --------
__global__ __launch_bounds__(256) void expmap_kernel() {
    int gw = blockIdx.x * 8 + (threadIdx.x >> 5);   // 0 .. 32768*16-1
    int lane = threadIdx.x & 31;
    size_t base = (size_t)gw * 64 + lane * 2;
    float2 v = *(float2*)(g_ek + base);
    float p = v.x * v.x + v.y * v.y;
#pragma unroll
    for (int off = 16; off; off >>= 1) p += __shfl_xor_sync(0xffffffffu, p, off);
    float n = sqrtf(fmaxf(p, EPS_));
    float s = tanhf(n) / n;
    v.x *= s;
    v.y *= s;
    *(float2*)(g_ek + base) = v;
}

// ---------------- hyperbolic path search: one CTA per (b, head) -------------
__global__ __launch_bounds__(256) void attn_kernel(const float* __restrict__ label,
                                                   const int* __restrict__ y,
                                                   const int* __restrict__ mask_text) {
    __shared__ __align__(16) float q_s[64];
    __shared__ float sq_q_s, fac_s;
    __shared__ float wm[8], wd[8];
    __shared__ __align__(16) float wacc[8][64];
    __shared__ int msk[1024];

    const int bh = blockIdx.x;
    const int b = bh >> 4;
    const int hh = bh & 15;
    const int tid = threadIdx.x;
    const int w = tid >> 5;
    const int lane = tid & 31;

    if (tid < 64) q_s[tid] = label[(size_t)y[b] * 64 + tid];
    for (int i = tid; i < 1024; i += 256) msk[i] = mask_text[b * 1024 + i];
    __syncthreads();
    if (w == 0) {
        float2 qv = *(float2*)(q_s + lane * 2);
        float p = qv.x * qv.x + qv.y * qv.y;
#pragma unroll
        for (int off = 16; off; off >>= 1) p += __shfl_xor_sync(0xffffffffu, p, off);
        if (lane == 0) sq_q_s = p;
    }
    __syncthreads();

    const float* ekb = g_ek + ((size_t)b * 1024 + hh * 64) * 1024;

    for (int layer = 0; layer < 4; layer++) {
        const float sqq = sq_q_s;
        const float aq = 1.f + sqq;
        const float idq = 1.f / fmaxf(1.f - sqq, EPS_);
        const float q0 = q_s[2 * lane], q1 = q_s[2 * lane + 1];

        float m = -INFINITY, den = 0.f, a0 = 0.f, a1 = 0.f;
        for (int t = 0; t < 128; t++) {
            const int idx = w * 128 + t;           // idx == reshaped ss position
            const float2 ev =
                *(const float2*)(ekb + (size_t)(idx >> 4) * 1024 + (idx & 15) * 64 + lane * 2);
            float pd = q0 * ev.x + q1 * ev.y;
            float ps = ev.x * ev.x + ev.y * ev.y;
#pragma unroll
            for (int off = 16; off; off >>= 1) {
                pd += __shfl_xor_sync(0xffffffffu, pd, off);
                ps += __shfl_xor_sync(0xffffffffu, ps, off);
            }
            const float idk = 1.f / fmaxf(1.f - ps, EPS_);
            const float x = (aq * (1.f + ps) - 4.f * pd) * idq * idk;
            const float tt = fmaxf(x - 1.f, 1e-6f);
            float score = -log1pf(tt + sqrtf(tt * (tt + 2.f)));
            if (!msk[idx]) score = -1e9f;
            const float nm = fmaxf(m, score);
            const float sc = __expf(m - nm);
            const float wg = __expf(score - nm);
            const float cw = wg * (1.f + ps) * idk;    // w * gamma
            const float cn = 2.f * wg * idk;           // w * gamma * (klein scale)
            den = den * sc + cw;
            a0 = a0 * sc + cn * ev.x;
            a1 = a1 * sc + cn * ev.y;
            m = nm;
        }
        wacc[w][2 * lane] = a0;
        wacc[w][2 * lane + 1] = a1;
        if (lane == 0) { wm[w] = m; wd[w] = den; }
        __syncthreads();

        if (tid < 64) {
            float M = wm[0];
#pragma unroll
            for (int ww = 1; ww < 8; ww++) M = fmaxf(M, wm[ww]);
            float num = 0.f, D = 0.f;
#pragma unroll
            for (int ww = 0; ww < 8; ww++) {
                float al = __expf(wm[ww] - M);
                num += al * wacc[ww][tid];
                D += al * wd[ww];
            }
            q_s[tid] = num / D;      // Einstein midpoint (Klein)
        }
        __syncthreads();
        if (w == 0) {
            float2 mv = *(float2*)(q_s + lane * 2);
            float p = mv.x * mv.x + mv.y * mv.y;
#pragma unroll
            for (int off = 16; off; off >>= 1) p += __shfl_xor_sync(0xffffffffu, p, off);
            if (lane == 0) {
                float r = 1.f / (1.f + sqrtf(fmaxf(1.f - p, EPS_)));   // k2p factor
                fac_s = r;
                sq_q_s = p * r * r;
            }
        }
        __syncthreads();
        if (tid < 64) q_s[tid] *= fac_s;
        __syncthreads();
    }
    if (tid < 64) g_qv[(size_t)bh * 64 + tid] = q_s[tid];
    if (tid == 0) g_sqq[bh] = sq_q_s;
}

// ---------------- label distances + aggregator MLP --------------------------
__global__ __launch_bounds__(128) void label_mlp_kernel(
    const float* __restrict__ label,
    const float* __restrict__ w1, const float* __restrict__ b1,
    const float* __restrict__ w2, const float* __restrict__ b2,
    const float* __restrict__ w3, const float* __restrict__ b3,
    const float* __restrict__ w4, const float* __restrict__ b4,
    const int* __restrict__ mask_label, float* __restrict__ out) {
    __shared__ float lab[128][65];
    __shared__ float qs[16 * 64];
    __shared__ float P[16], Qc[16];
    __shared__ float sw1[512], sb1[32], sw2[1024], sb2[32], sw3[512], sb3[16], sw4[16], sb4s[1];

    const int b = blockIdx.y;
    const int base = blockIdx.x * 128;
    const int tid = threadIdx.x;

    for (int i = tid; i < 128 * 64; i += 128) lab[i >> 6][i & 63] = label[(size_t)base * 64 + i];
    for (int i = tid; i < 1024; i += 128) qs[i] = g_qv[(size_t)b * 1024 + i];
    if (tid < 16) {
        float s = g_sqq[b * 16 + tid];
        float inv = 1.f / fmaxf(1.f - s, EPS_);
        P[tid] = (1.f + s) * inv;
        Qc[tid] = 4.f * inv;
    }
    for (int i = tid; i < 512; i += 128) sw1[i] = w1[i];
    for (int i = tid; i < 1024; i += 128) sw2[i] = w2[i];
    for (int i = tid; i < 512; i += 128) sw3[i] = w3[i];
    if (tid < 32) { sb1[tid] = b1[tid]; sb2[tid] = b2[tid]; }
    if (tid < 16) { sb3[tid] = b3[tid]; sw4[tid] = w4[tid]; }
    if (tid == 0) sb4s[0] = b4[0];
    __syncthreads();

    float sq_l = 0.f;
#pragma unroll 8
    for (int d = 0; d < 64; d++) { float v = lab[tid][d]; sq_l += v * v; }
    const float invl = 1.f / fmaxf(1.f - sq_l, EPS_);
    const float L1 = (1.f + sq_l) * invl;

    float dh[16];
#pragma unroll
    for (int h = 0; h < 16; h++) {
        float dot = 0.f;
#pragma unroll 8
        for (int d = 0; d < 64; d++) dot += qs[h * 64 + d] * lab[tid][d];
        float x = P[h] * L1 - Qc[h] * invl * dot;
        float tt = fmaxf(x - 1.f, 1e-6f);
        dh[h] = log1pf(tt + sqrtf(tt * (tt + 2.f)));
    }
    float x1[32];
#pragma unroll
    for (int j = 0; j < 32; j++) {
        float a = sb1[j];
#pragma unroll
        for (int h = 0; h < 16; h++) a += dh[h] * sw1[h * 32 + j];
        x1[j] = fmaxf(a, 0.f);
    }
    float x2[32];
#pragma unroll
    for (int j = 0; j < 32; j++) {
        float a = sb2[j];
#pragma unroll
        for (int i = 0; i < 32; i++) a += x1[i] * sw2[i * 32 + j];
        x2[j] = fmaxf(a, 0.f);
    }
    float x3[16];
#pragma unroll
    for (int j = 0; j < 16; j++) {
        float a = sb3[j];
#pragma unroll
        for (int i = 0; i < 32; i++) a += x2[i] * sw3[i * 16 + j];
        x3[j] = fmaxf(a, 0.f);
    }
    float val = sb4s[0];
#pragma unroll
    for (int h = 0; h < 16; h++) val += x3[h] * sw4[h];

    const int n = base + tid;
    out[(size_t)b * NLABEL + n] = (mask_label[(size_t)b * NLABEL + n] > 0) ? val : -500.f;
}

// ---------------- launch -----------------------------------------------------
extern "C" void kernel_launch(void* const* d_in, const int* in_sizes, int n_in,
                              void* d_out, int out_size) {
    const float* e     = (const float*)d_in[0];
    const float* label = (const float*)d_in[1];
    const float* tc_w1 = (const float*)d_in[2];
    const float* tc_b1 = (const float*)d_in[3];
    const float* tc_w2 = (const float*)d_in[4];
    const float* tc_b2 = (const float*)d_in[5];
    const float* hyp_w = (const float*)d_in[6];
    const float* hyp_b = (const float*)d_in[7];
    const float* aw1 = (const float*)d_in[8];
    const float* ab1 = (const float*)d_in[9];
    const float* aw2 = (const float*)d_in[10];
    const float* ab2 = (const float*)d_in[11];
    const float* aw3 = (const float*)d_in[12];
    const float* ab3 = (const float*)d_in[13];
    const float* aw4 = (const float*)d_in[14];
    const float* ab4 = (const float*)d_in[15];
    const int* y  = (const int*)d_in[16];
    const int* mt = (const int*)d_in[17];
    const int* ml = (const int*)d_in[18];
    float* out = (float*)d_out;

    float *h1p, *ekp, *w2fp, *b2fp;
    cudaGetSymbolAddress((void**)&h1p, g_h1);
    cudaGetSymbolAddress((void**)&ekp, g_ek);
    cudaGetSymbolAddress((void**)&w2fp, g_w2f);
    cudaGetSymbolAddress((void**)&b2fp, g_b2f);

    fold_w2_kernel<<<2048, 256>>>(tc_w2, hyp_w);
    fold_b2_kernel<<<4, 256>>>(tc_b2, hyp_w, hyp_b);

    // GEMM1: h1 = relu(e @ tc_w1 + tc_b1)   [32768,1024]x[1024,2048]
    sgemm_kernel<true><<<dim3(2048 / BN, MROWS / BM), 256>>>(e, tc_w1, tc_b1, h1p,
                                                             MROWS, 2048, 1024);
    // GEMM2: ek_pre = h1 @ w2f + b2f        [32768,2048]x[2048,1024]
    sgemm_kernel<false><<<dim3(1024 / BN, MROWS / BM), 256>>>(h1p, w2fp, b2fp, ekp,
                                                              MROWS, 1024, 2048);
    expmap_kernel<<<MROWS * 16 / 8, 256>>>();
    attn_kernel<<<512, 256>>>(label, y, mt);
    label_mlp_kernel<<<dim3(NLABEL / 128, BB), 128>>>(label, aw1, ab1, aw2, ab2,
                                                      aw3, ab3, aw4, ab4, ml, out);
}

// round 3
// speedup vs baseline: 1.7999x; 1.7999x over previous
#include <cuda_runtime.h>
#include <cuda_bf16.h>
#include <math.h>
#include <stdint.h>

// Problem constants
#define BBATCH 32
#define NLABEL 8192
#define MROWS 32768
#define EPS_ 1e-12f

// ---------------- device scratch ----------------
__device__ __nv_bfloat16 g_ehi[(size_t)MROWS * 1024];
__device__ __nv_bfloat16 g_elo[(size_t)MROWS * 1024];
__device__ __nv_bfloat16 g_h1hi[(size_t)MROWS * 2048];
__device__ __nv_bfloat16 g_h1lo[(size_t)MROWS * 2048];
__device__ float g_ek[(size_t)MROWS * 1024];
__device__ float g_w2f[2048 * 1024];
__device__ float g_b2f[1024];
__device__ __nv_bfloat16 g_w1t_hi[2048 * 1024];
__device__ __nv_bfloat16 g_w1t_lo[2048 * 1024];
__device__ __nv_bfloat16 g_w2t_hi[1024 * 2048];
__device__ __nv_bfloat16 g_w2t_lo[1024 * 2048];
__device__ float g_qv[512 * 64];
__device__ float g_sqq[512];

// ---------------- PTX helpers ----------------
__device__ __forceinline__ uint32_t smem_u32(const void* p) {
    uint32_t a;
    asm("{ .reg .u64 t; cvta.to.shared.u64 t, %1; cvt.u32.u64 %0, t; }" : "=r"(a) : "l"(p));
    return a;
}
__device__ __forceinline__ void cpa16(uint32_t saddr, const void* g) {
    asm volatile("cp.async.cg.shared.global [%0], [%1], 16;" :: "r"(saddr), "l"(g));
}
#define CP_COMMIT() asm volatile("cp.async.commit_group;" ::: "memory")

#define LDSM4(r0, r1, r2, r3, addr) \
    asm volatile("ldmatrix.sync.aligned.m8n8.x4.shared.b16 {%0,%1,%2,%3}, [%4];" \
                 : "=r"(r0), "=r"(r1), "=r"(r2), "=r"(r3) : "r"(addr))

#define MMA16816(c, a0, a1, a2, a3, b0, b1) \
    asm volatile( \
        "mma.sync.aligned.m16n8k16.row.col.f32.bf16.bf16.f32 " \
        "{%0,%1,%2,%3}, {%4,%5,%6,%7}, {%8,%9}, {%0,%1,%2,%3};" \
        : "+f"((c)[0]), "+f"((c)[1]), "+f"((c)[2]), "+f"((c)[3]) \
        : "r"(a0), "r"(a1), "r"(a2), "r"(a3), "r"(b0), "r"(b1))

// ---------------- weight folding ----------------
__global__ void fold_w2_kernel(const float* __restrict__ tc_w2,
                               const float* __restrict__ hyp_w) {
    __shared__ float hw[64 * 64];
    __shared__ float row[1024];
    int k = blockIdx.x;
    int tid = threadIdx.x;
    for (int i = tid; i < 4096; i += 256) hw[i] = hyp_w[i];
    for (int i = tid; i < 1024; i += 256) row[i] = tc_w2[(size_t)k * 1024 + i];
    __syncthreads();
#pragma unroll
    for (int t = 0; t < 4; t++) {
        int c = tid + t * 256;
        int j = c >> 6, dp = c & 63;
        float acc = 0.f;
#pragma unroll 8
        for (int d = 0; d < 64; d++) acc += row[j * 64 + d] * hw[d * 64 + dp];
        g_w2f[(size_t)k * 1024 + c] = acc;
    }
}

__global__ void fold_b2_kernel(const float* __restrict__ tc_b2,
                               const float* __restrict__ hyp_w,
                               const float* __restrict__ hyp_b) {
    int c = blockIdx.x * 256 + threadIdx.x;
    if (c < 1024) {
        int j = c >> 6, dp = c & 63;
        float acc = hyp_b[dp];
        for (int d = 0; d < 64; d++) acc += tc_b2[j * 64 + d] * hyp_w[d * 64 + dp];
        g_b2f[c] = acc;
    }
}

// ---------------- fp32 -> bf16 hi/lo split ----------------
__global__ __launch_bounds__(256) void split_kernel(const float* __restrict__ in,
                                                    __nv_bfloat16* __restrict__ hi,
                                                    __nv_bfloat16* __restrict__ lo, int n4) {
    int i = blockIdx.x * 256 + threadIdx.x;
    if (i < n4) {
        float4 v = ((const float4*)in)[i];
        float f[4] = {v.x, v.y, v.z, v.w};
        unsigned uh[2], ul[2];
#pragma unroll
        for (int q = 0; q < 2; q++) {
            __nv_bfloat16 h0 = __float2bfloat16(f[2 * q]);
            __nv_bfloat16 h1 = __float2bfloat16(f[2 * q + 1]);
            __nv_bfloat16 l0 = __float2bfloat16(f[2 * q] - __bfloat162float(h0));
            __nv_bfloat16 l1 = __float2bfloat16(f[2 * q + 1] - __bfloat162float(h1));
            uh[q] = ((unsigned)__bfloat16_as_ushort(h1) << 16) | __bfloat16_as_ushort(h0);
            ul[q] = ((unsigned)__bfloat16_as_ushort(l1) << 16) | __bfloat16_as_ushort(l0);
        }
        ((uint2*)hi)[i] = make_uint2(uh[0], uh[1]);
        ((uint2*)lo)[i] = make_uint2(ul[0], ul[1]);
    }
}

// ---------------- transpose + split ----------------
__global__ void transpose_split_kernel(const float* __restrict__ in,
                                       __nv_bfloat16* __restrict__ ohi,
                                       __nv_bfloat16* __restrict__ olo, int R, int C) {
    __shared__ float t[32][33];
    int cb = blockIdx.x * 32, rb = blockIdx.y * 32;
    int x = threadIdx.x, y = threadIdx.y;
#pragma unroll
    for (int i = y; i < 32; i += 8) t[i][x] = in[(size_t)(rb + i) * C + cb + x];
    __syncthreads();
#pragma unroll
    for (int i = y; i < 32; i += 8) {
        float v = t[x][i];
        __nv_bfloat16 h = __float2bfloat16(v);
        __nv_bfloat16 l = __float2bfloat16(v - __bfloat162float(h));
        size_t o = (size_t)(cb + i) * R + rb + x;
        ohi[o] = h;
        olo[o] = l;
    }
}

// ---------------- mma.sync split-precision GEMM ------------------------------
// C[M,N] = A(hi+lo)[M,K] @ B(hi+lo)[N,K]^T + bias
// EPI=0: relu + bf16 hi/lo split store;  EPI=1: expmap0 + fp32 store
// SMEM: 2 stages x 4 tiles (Ahi,Alo,Bhi,Blo) of 128x32 bf16 in atom-major layout:
//   unit16B index = rg*32 + seg*8 + rin  (rg=row>>3, seg=k16Bseg, rin=row&7)
#define STG_BYTES 32768
#define TIL_BYTES 8192

template <int EPI>
__global__ __launch_bounds__(256, 2) void gemm_mma_kernel(
    const __nv_bfloat16* __restrict__ Ahi, const __nv_bfloat16* __restrict__ Alo,
    const __nv_bfloat16* __restrict__ Bhi, const __nv_bfloat16* __restrict__ Blo,
    const float* __restrict__ bias, float* __restrict__ Cf,
    __nv_bfloat16* __restrict__ Chi, __nv_bfloat16* __restrict__ Clo,
    int M, int N, int K) {
    extern __shared__ char dsm[];
    __shared__ float sbias[128];

    const int tid = threadIdx.x;
    const int wid = tid >> 5, lane = tid & 31;
    const int wm = wid >> 2;       // 0..1 (64 rows each)
    const int wn = wid & 3;        // 0..3 (32 cols each)
    const int n0 = blockIdx.x * 128;
    const int m0 = blockIdx.y * 128;
    const uint32_t sb = smem_u32(dsm);

    if (tid < 128) sbias[tid] = bias[n0 + tid];

    // lane offsets for ldmatrix (atom-major layout)
    const int g = lane >> 3, rin = lane & 7;
    const uint32_t laneAoff = (((uint32_t)(g & 1)) * 32 + ((uint32_t)(g >> 1)) * 8 + rin) * 16;
    const uint32_t laneBoff = (((uint32_t)(g >> 1)) * 32 + ((uint32_t)(g & 1)) * 8 + rin) * 16;

    float acc[4][4][4];
#pragma unroll
    for (int i = 0; i < 4; i++)
#pragma unroll
        for (int n = 0; n < 4; n++)
#pragma unroll
            for (int r = 0; r < 4; r++) acc[i][n][r] = 0.f;

    const int nchunk = K >> 5;

    // ---- stage loader (8 x cp.async.16 per thread) ----
    auto load_stage = [&](int buf, int kc) {
        const uint32_t sbase = sb + buf * STG_BYTES;
#pragma unroll
        for (int it = 0; it < 8; it++) {
            int uid = tid + it * 256;
            int tile = uid >> 9;
            int rem = uid & 511;
            int rg = rem >> 5, seg = (rem >> 3) & 3, rr = rem & 7;
            int lrow = rg * 8 + rr;
            const __nv_bfloat16* src = (tile == 0) ? Ahi : (tile == 1) ? Alo
                                        : (tile == 2) ? Bhi : Blo;
            int grow = ((tile < 2) ? m0 : n0) + lrow;
            cpa16(sbase + tile * TIL_BYTES + rem * 16,
                  src + (size_t)grow * K + kc * 32 + seg * 8);
        }
        CP_COMMIT();
    };

    load_stage(0, 0);

    for (int kc = 0; kc < nchunk; kc++) {
        const int buf = kc & 1;
        if (kc + 1 < nchunk) {
            load_stage(buf ^ 1, kc + 1);
            asm volatile("cp.async.wait_group 1;" ::: "memory");
        } else {
            asm volatile("cp.async.wait_group 0;" ::: "memory");
        }
        __syncthreads();

        const uint32_t tAhi = sb + buf * STG_BYTES;
        const uint32_t tAlo = tAhi + TIL_BYTES;
        const uint32_t tBhi = tAhi + 2 * TIL_BYTES;
        const uint32_t tBlo = tAhi + 3 * TIL_BYTES;
        const uint32_t aw = (uint32_t)wm * 4096;   // (8*wm)*512
        const uint32_t bw = (uint32_t)wn * 2048;   // (4*wn)*512

#pragma unroll
        for (int j = 0; j < 2; j++) {
            uint32_t ah[16], bb[8];
            const uint32_t jo = (uint32_t)j * 256;
            // Ahi frags
#pragma unroll
            for (int i = 0; i < 4; i++)
                LDSM4(ah[4 * i], ah[4 * i + 1], ah[4 * i + 2], ah[4 * i + 3],
                      tAhi + aw + (uint32_t)i * 1024 + jo + laneAoff);
            // Bhi frags
#pragma unroll
            for (int p = 0; p < 2; p++)
                LDSM4(bb[4 * p], bb[4 * p + 1], bb[4 * p + 2], bb[4 * p + 3],
                      tBhi + bw + (uint32_t)p * 1024 + jo + laneBoff);
#pragma unroll
            for (int i = 0; i < 4; i++)
#pragma unroll
                for (int n = 0; n < 4; n++)
                    MMA16816(acc[i][n], ah[4 * i], ah[4 * i + 1], ah[4 * i + 2], ah[4 * i + 3],
                             bb[2 * n], bb[2 * n + 1]);
            // Blo frags (overwrite bb)
#pragma unroll
            for (int p = 0; p < 2; p++)
                LDSM4(bb[4 * p], bb[4 * p + 1], bb[4 * p + 2], bb[4 * p + 3],
                      tBlo + bw + (uint32_t)p * 1024 + jo + laneBoff);
#pragma unroll
            for (int i = 0; i < 4; i++)
#pragma unroll
                for (int n = 0; n < 4; n++)
                    MMA16816(acc[i][n], ah[4 * i], ah[4 * i + 1], ah[4 * i + 2], ah[4 * i + 3],
                             bb[2 * n], bb[2 * n + 1]);
            // Alo frags (overwrite ah), reload Bhi
#pragma unroll
            for (int i = 0; i < 4; i++)
                LDSM4(ah[4 * i], ah[4 * i + 1], ah[4 * i + 2], ah[4 * i + 3],
                      tAlo + aw + (uint32_t)i * 1024 + jo + laneAoff);
#pragma unroll
            for (int p = 0; p < 2; p++)
                LDSM4(bb[4 * p], bb[4 * p + 1], bb[4 * p + 2], bb[4 * p + 3],
                      tBhi + bw + (uint32_t)p * 1024 + jo + laneBoff);
#pragma unroll
            for (int i = 0; i < 4; i++)
#pragma unroll
                for (int n = 0; n < 4; n++)
                    MMA16816(acc[i][n], ah[4 * i], ah[4 * i + 1], ah[4 * i + 2], ah[4 * i + 3],
                             bb[2 * n], bb[2 * n + 1]);
        }
        __syncthreads();
    }

    // ---------------- epilogue ----------------
    if (EPI == 0) {
        // relu + bf16 hi/lo split, staged in SMEM for coalesced output
        __nv_bfloat16* sh = (__nv_bfloat16*)dsm;              // [128][128]
        __nv_bfloat16* sl = (__nv_bfloat16*)(dsm + 32768);    // [128][128]
#pragma unroll
        for (int i = 0; i < 4; i++) {
            const int r0 = 64 * wm + 16 * i + (lane >> 2);
#pragma unroll
            for (int n = 0; n < 4; n++) {
                const int col = 32 * wn + 8 * n + (lane & 3) * 2;
#pragma unroll
                for (int half = 0; half < 2; half++) {
                    const int rr = r0 + half * 8;
                    float v0 = fmaxf(acc[i][n][2 * half] + sbias[col], 0.f);
                    float v1 = fmaxf(acc[i][n][2 * half + 1] + sbias[col + 1], 0.f);
                    __nv_bfloat16 h0 = __float2bfloat16(v0);
                    __nv_bfloat16 h1 = __float2bfloat16(v1);
                    __nv_bfloat16 l0 = __float2bfloat16(v0 - __bfloat162float(h0));
                    __nv_bfloat16 l1 = __float2bfloat16(v1 - __bfloat162float(h1));
                    *(uint32_t*)(sh + rr * 128 + col) =
                        ((uint32_t)__bfloat16_as_ushort(h1) << 16) | __bfloat16_as_ushort(h0);
                    *(uint32_t*)(sl + rr * 128 + col) =
                        ((uint32_t)__bfloat16_as_ushort(l1) << 16) | __bfloat16_as_ushort(l0);
                }
            }
        }
        __syncthreads();
#pragma unroll
        for (int it = 0; it < 8; it++) {
            int idx = tid + it * 256;          // 2048 uint4 per buffer
            int row = idx >> 4, seg = idx & 15;
            uint4 vh = ((const uint4*)dsm)[idx];
            uint4 vl = ((const uint4*)(dsm + 32768))[idx];
            *(uint4*)(Chi + (size_t)(m0 + row) * N + n0 + seg * 8) = vh;
            *(uint4*)(Clo + (size_t)(m0 + row) * N + n0 + seg * 8) = vl;
        }
    } else {
        // stage fp32 (pad-130), then fused expmap0 per 64-d vector
        float* stf = (float*)dsm;
#pragma unroll
        for (int i = 0; i < 4; i++) {
            const int r0 = 64 * wm + 16 * i + (lane >> 2);
#pragma unroll
            for (int n = 0; n < 4; n++) {
                const int col = 32 * wn + 8 * n + (lane & 3) * 2;
#pragma unroll
                for (int half = 0; half < 2; half++) {
                    const int rr = r0 + half * 8;
                    stf[rr * 130 + col] = acc[i][n][2 * half] + sbias[col];
                    stf[rr * 130 + col + 1] = acc[i][n][2 * half + 1] + sbias[col + 1];
                }
            }
        }
        __syncthreads();
        const int row = tid >> 1, grp = tid & 1;
        const float* src = stf + row * 130 + grp * 64;
        float v[64];
        float sum = 0.f;
#pragma unroll
        for (int q = 0; q < 32; q++) {
            float2 p = *(const float2*)(src + 2 * q);
            v[2 * q] = p.x;
            v[2 * q + 1] = p.y;
            sum += p.x * p.x + p.y * p.y;
        }
        float nrm = sqrtf(fmaxf(sum, EPS_));
        float s = tanhf(nrm) / nrm;
        float* dst = Cf + (size_t)(m0 + row) * N + n0 + grp * 64;
#pragma unroll
        for (int q = 0; q < 16; q++)
            *(float4*)(dst + 4 * q) = make_float4(v[4 * q] * s, v[4 * q + 1] * s,
                                                  v[4 * q + 2] * s, v[4 * q + 3] * s);
    }
}

// ---------------- hyperbolic path search: one CTA per (b, head) -------------
__global__ __launch_bounds__(256) void attn_kernel(const float* __restrict__ label,
                                                   const int* __restrict__ y,
                                                   const int* __restrict__ mask_text) {
    __shared__ __align__(16) float q_s[64];
    __shared__ float sq_q_s, fac_s;
    __shared__ float wm[8], wd[8];
    __shared__ __align__(16) float wacc[8][64];
    __shared__ int msk[1024];

    const int bh = blockIdx.x;
    const int b = bh >> 4;
    const int hh = bh & 15;
    const int tid = threadIdx.x;
    const int w = tid >> 5;
    const int lane = tid & 31;

    if (tid < 64) q_s[tid] = label[(size_t)y[b] * 64 + tid];
    for (int i = tid; i < 1024; i += 256) msk[i] = mask_text[b * 1024 + i];
    __syncthreads();
    if (w == 0) {
        float2 qv = *(float2*)(q_s + lane * 2);
        float p = qv.x * qv.x + qv.y * qv.y;
#pragma unroll
        for (int off = 16; off; off >>= 1) p += __shfl_xor_sync(0xffffffffu, p, off);
        if (lane == 0) sq_q_s = p;
    }
    __syncthreads();

    const float* ekb = g_ek + ((size_t)b * 1024 + hh * 64) * 1024;

    for (int layer = 0; layer < 4; layer++) {
        const float sqq = sq_q_s;
        const float aq = 1.f + sqq;
        const float idq = 1.f / fmaxf(1.f - sqq, EPS_);
        const float q0 = q_s[2 * lane], q1 = q_s[2 * lane + 1];

        float m = -INFINITY, den = 0.f, a0 = 0.f, a1 = 0.f;
        for (int t = 0; t < 128; t++) {
            const int idx = w * 128 + t;
            const float2 ev =
                *(const float2*)(ekb + (size_t)(idx >> 4) * 1024 + (idx & 15) * 64 + lane * 2);
            float pd = q0 * ev.x + q1 * ev.y;
            float ps = ev.x * ev.x + ev.y * ev.y;
#pragma unroll
            for (int off = 16; off; off >>= 1) {
                pd += __shfl_xor_sync(0xffffffffu, pd, off);
                ps += __shfl_xor_sync(0xffffffffu, ps, off);
            }
            const float idk = 1.f / fmaxf(1.f - ps, EPS_);
            const float x = (aq * (1.f + ps) - 4.f * pd) * idq * idk;
            const float tt = fmaxf(x - 1.f, 1e-6f);
            float score = -log1pf(tt + sqrtf(tt * (tt + 2.f)));
            if (!msk[idx]) score = -1e9f;
            const float nm = fmaxf(m, score);
            const float sc = __expf(m - nm);
            const float wg = __expf(score - nm);
            const float cw = wg * (1.f + ps) * idk;
            const float cn = 2.f * wg * idk;
            den = den * sc + cw;
            a0 = a0 * sc + cn * ev.x;
            a1 = a1 * sc + cn * ev.y;
            m = nm;
        }
        wacc[w][2 * lane] = a0;
        wacc[w][2 * lane + 1] = a1;
        if (lane == 0) { wm[w] = m; wd[w] = den; }
        __syncthreads();

        if (tid < 64) {
            float M = wm[0];
#pragma unroll
            for (int ww = 1; ww < 8; ww++) M = fmaxf(M, wm[ww]);
            float num = 0.f, D = 0.f;
#pragma unroll
            for (int ww = 0; ww < 8; ww++) {
                float al = __expf(wm[ww] - M);
                num += al * wacc[ww][tid];
                D += al * wd[ww];
            }
            q_s[tid] = num / D;
        }
        __syncthreads();
        if (w == 0) {
            float2 mv = *(float2*)(q_s + lane * 2);
            float p = mv.x * mv.x + mv.y * mv.y;
#pragma unroll
            for (int off = 16; off; off >>= 1) p += __shfl_xor_sync(0xffffffffu, p, off);
            if (lane == 0) {
                float r = 1.f / (1.f + sqrtf(fmaxf(1.f - p, EPS_)));
                fac_s = r;
                sq_q_s = p * r * r;
            }
        }
        __syncthreads();
        if (tid < 64) q_s[tid] *= fac_s;
        __syncthreads();
    }
    if (tid < 64) g_qv[(size_t)bh * 64 + tid] = q_s[tid];
    if (tid == 0) g_sqq[bh] = sq_q_s;
}

// ---------------- label distances + aggregator MLP --------------------------
__global__ __launch_bounds__(128) void label_mlp_kernel(
    const float* __restrict__ label,
    const float* __restrict__ w1, const float* __restrict__ b1,
    const float* __restrict__ w2, const float* __restrict__ b2,
    const float* __restrict__ w3, const float* __restrict__ b3,
    const float* __restrict__ w4, const float* __restrict__ b4,
    const int* __restrict__ mask_label, float* __restrict__ out) {
    __shared__ float lab[128][65];
    __shared__ float qs[16 * 64];
    __shared__ float P[16], Qc[16];
    __shared__ float sw1[512], sb1[32], sw2[1024], sb2[32], sw3[512], sb3[16], sw4[16], sb4s[1];

    const int b = blockIdx.y;
    const int base = blockIdx.x * 128;
    const int tid = threadIdx.x;

    for (int i = tid; i < 128 * 64; i += 128) lab[i >> 6][i & 63] = label[(size_t)base * 64 + i];
    for (int i = tid; i < 1024; i += 128) qs[i] = g_qv[(size_t)b * 1024 + i];
    if (tid < 16) {
        float s = g_sqq[b * 16 + tid];
        float inv = 1.f / fmaxf(1.f - s, EPS_);
        P[tid] = (1.f + s) * inv;
        Qc[tid] = 4.f * inv;
    }
    for (int i = tid; i < 512; i += 128) sw1[i] = w1[i];
    for (int i = tid; i < 1024; i += 128) sw2[i] = w2[i];
    for (int i = tid; i < 512; i += 128) sw3[i] = w3[i];
    if (tid < 32) { sb1[tid] = b1[tid]; sb2[tid] = b2[tid]; }
    if (tid < 16) { sb3[tid] = b3[tid]; sw4[tid] = w4[tid]; }
    if (tid == 0) sb4s[0] = b4[0];
    __syncthreads();

    float sq_l = 0.f;
#pragma unroll 8
    for (int d = 0; d < 64; d++) { float v = lab[tid][d]; sq_l += v * v; }
    const float invl = 1.f / fmaxf(1.f - sq_l, EPS_);
    const float L1 = (1.f + sq_l) * invl;

    float dh[16];
#pragma unroll
    for (int h = 0; h < 16; h++) {
        float dot = 0.f;
#pragma unroll 8
        for (int d = 0; d < 64; d++) dot += qs[h * 64 + d] * lab[tid][d];
        float x = P[h] * L1 - Qc[h] * invl * dot;
        float tt = fmaxf(x - 1.f, 1e-6f);
        dh[h] = log1pf(tt + sqrtf(tt * (tt + 2.f)));
    }
    float x1[32];
#pragma unroll
    for (int j = 0; j < 32; j++) {
        float a = sb1[j];
#pragma unroll
        for (int h = 0; h < 16; h++) a += dh[h] * sw1[h * 32 + j];
        x1[j] = fmaxf(a, 0.f);
    }
    float x2[32];
#pragma unroll
    for (int j = 0; j < 32; j++) {
        float a = sb2[j];
#pragma unroll
        for (int i = 0; i < 32; i++) a += x1[i] * sw2[i * 32 + j];
        x2[j] = fmaxf(a, 0.f);
    }
    float x3[16];
#pragma unroll
    for (int j = 0; j < 16; j++) {
        float a = sb3[j];
#pragma unroll
        for (int i = 0; i < 32; i++) a += x2[i] * sw3[i * 16 + j];
        x3[j] = fmaxf(a, 0.f);
    }
    float val = sb4s[0];
#pragma unroll
    for (int h = 0; h < 16; h++) val += x3[h] * sw4[h];

    const int n = base + tid;
    out[(size_t)b * NLABEL + n] = (mask_label[(size_t)b * NLABEL + n] > 0) ? val : -500.f;
}

// ---------------- launch -----------------------------------------------------
extern "C" void kernel_launch(void* const* d_in, const int* in_sizes, int n_in,
                              void* d_out, int out_size) {
    const float* e = (const float*)d_in[0];
    const float* label = (const float*)d_in[1];
    const float* tc_w1 = (const float*)d_in[2];
    const float* tc_b1 = (const float*)d_in[3];
    const float* tc_w2 = (const float*)d_in[4];
    const float* tc_b2 = (const float*)d_in[5];
    const float* hyp_w = (const float*)d_in[6];
    const float* hyp_b = (const float*)d_in[7];
    const float* aw1 = (const float*)d_in[8];
    const float* ab1 = (const float*)d_in[9];
    const float* aw2 = (const float*)d_in[10];
    const float* ab2 = (const float*)d_in[11];
    const float* aw3 = (const float*)d_in[12];
    const float* ab3 = (const float*)d_in[13];
    const float* aw4 = (const float*)d_in[14];
    const float* ab4 = (const float*)d_in[15];
    const int* y = (const int*)d_in[16];
    const int* mt = (const int*)d_in[17];
    const int* ml = (const int*)d_in[18];
    float* out = (float*)d_out;

    __nv_bfloat16 *ehi, *elo, *h1hi, *h1lo, *w1th, *w1tl, *w2th, *w2tl;
    float *ekp, *w2fp, *b2fp;
    cudaGetSymbolAddress((void**)&ehi, g_ehi);
    cudaGetSymbolAddress((void**)&elo, g_elo);
    cudaGetSymbolAddress((void**)&h1hi, g_h1hi);
    cudaGetSymbolAddress((void**)&h1lo, g_h1lo);
    cudaGetSymbolAddress((void**)&w1th, g_w1t_hi);
    cudaGetSymbolAddress((void**)&w1tl, g_w1t_lo);
    cudaGetSymbolAddress((void**)&w2th, g_w2t_hi);
    cudaGetSymbolAddress((void**)&w2tl, g_w2t_lo);
    cudaGetSymbolAddress((void**)&ekp, g_ek);
    cudaGetSymbolAddress((void**)&w2fp, g_w2f);
    cudaGetSymbolAddress((void**)&b2fp, g_b2f);

    const int smem_bytes = 66560;   // max(2*32KB stages, 128*130*4 staging)
    cudaFuncSetAttribute(gemm_mma_kernel<0>, cudaFuncAttributeMaxDynamicSharedMemorySize,
                         smem_bytes);
    cudaFuncSetAttribute(gemm_mma_kernel<1>, cudaFuncAttributeMaxDynamicSharedMemorySize,
                         smem_bytes);

    // prep
    fold_w2_kernel<<<2048, 256>>>(tc_w2, hyp_w);
    fold_b2_kernel<<<4, 256>>>(tc_b2, hyp_w, hyp_b);
    transpose_split_kernel<<<dim3(2048 / 32, 1024 / 32), dim3(32, 8)>>>(tc_w1, w1th, w1tl,
                                                                        1024, 2048);
    transpose_split_kernel<<<dim3(1024 / 32, 2048 / 32), dim3(32, 8)>>>(w2fp, w2th, w2tl,
                                                                        2048, 1024);
    split_kernel<<<(MROWS * 1024 / 4 + 255) / 256, 256>>>(e, ehi, elo, MROWS * 1024 / 4);

    // GEMM1: h1 = relu(e @ w1 + b1) -> bf16 hi/lo
    gemm_mma_kernel<0><<<dim3(16, 256), 256, smem_bytes>>>(
        ehi, elo, w1th, w1tl, tc_b1, nullptr, h1hi, h1lo, MROWS, 2048, 1024);
    // GEMM2: ek = expmap0(h1 @ w2f + b2f) -> fp32
    gemm_mma_kernel<1><<<dim3(8, 256), 256, smem_bytes>>>(
        h1hi, h1lo, w2th, w2tl, b2fp, ekp, nullptr, nullptr, MROWS, 1024, 2048);

    attn_kernel<<<512, 256>>>(label, y, mt);
    label_mlp_kernel<<<dim3(NLABEL / 128, BBATCH), 128>>>(label, aw1, ab1, aw2, ab2,
                                                          aw3, ab3, aw4, ab4, ml, out);
}

// round 4
// speedup vs baseline: 3.5371x; 1.9652x over previous
#include <cuda_runtime.h>
#include <cuda_bf16.h>
#include <math.h>
#include <stdint.h>

// Problem constants
#define BBATCH 32
#define NLABEL 8192
#define MROWS 32768
#define EPS_ 1e-12f

// ---------------- device scratch ----------------
__device__ __nv_bfloat16 g_e16[(size_t)MROWS * 1024];
__device__ __nv_bfloat16 g_h1[(size_t)MROWS * 2048];
__device__ float g_ek[(size_t)MROWS * 1024];
__device__ float g_w2f[2048 * 1024];
__device__ float g_b2f[1024];
__device__ __nv_bfloat16 g_w1t[2048 * 1024];
__device__ __nv_bfloat16 g_w2t[1024 * 2048];
__device__ float g_qv[512 * 64];
__device__ float g_sqq[512];

// ---------------- PTX helpers ----------------
__device__ __forceinline__ uint32_t smem_u32(const void* p) {
    uint32_t a;
    asm("{ .reg .u64 t; cvta.to.shared.u64 t, %1; cvt.u32.u64 %0, t; }" : "=r"(a) : "l"(p));
    return a;
}
__device__ __forceinline__ void cpa16(uint32_t saddr, const void* g) {
    asm volatile("cp.async.cg.shared.global [%0], [%1], 16;" :: "r"(saddr), "l"(g));
}
#define CP_COMMIT() asm volatile("cp.async.commit_group;" ::: "memory")

#define LDSM4(r0, r1, r2, r3, addr) \
    asm volatile("ldmatrix.sync.aligned.m8n8.x4.shared.b16 {%0,%1,%2,%3}, [%4];" \
                 : "=r"(r0), "=r"(r1), "=r"(r2), "=r"(r3) : "r"(addr))

#define MMA16816(c, a0, a1, a2, a3, b0, b1) \
    asm volatile( \
        "mma.sync.aligned.m16n8k16.row.col.f32.bf16.bf16.f32 " \
        "{%0,%1,%2,%3}, {%4,%5,%6,%7}, {%8,%9}, {%0,%1,%2,%3};" \
        : "+f"((c)[0]), "+f"((c)[1]), "+f"((c)[2]), "+f"((c)[3]) \
        : "r"(a0), "r"(a1), "r"(a2), "r"(a3), "r"(b0), "r"(b1))

// ---------------- weight folding ----------------
__global__ void fold_w2_kernel(const float* __restrict__ tc_w2,
                               const float* __restrict__ hyp_w) {
    __shared__ float hw[64 * 64];
    __shared__ float row[1024];
    int k = blockIdx.x;
    int tid = threadIdx.x;
    for (int i = tid; i < 4096; i += 256) hw[i] = hyp_w[i];
    for (int i = tid; i < 1024; i += 256) row[i] = tc_w2[(size_t)k * 1024 + i];
    __syncthreads();
#pragma unroll
    for (int t = 0; t < 4; t++) {
        int c = tid + t * 256;
        int j = c >> 6, dp = c & 63;
        float acc = 0.f;
#pragma unroll 8
        for (int d = 0; d < 64; d++) acc += row[j * 64 + d] * hw[d * 64 + dp];
        g_w2f[(size_t)k * 1024 + c] = acc;
    }
}

__global__ void fold_b2_kernel(const float* __restrict__ tc_b2,
                               const float* __restrict__ hyp_w,
                               const float* __restrict__ hyp_b) {
    int c = blockIdx.x * 256 + threadIdx.x;
    if (c < 1024) {
        int j = c >> 6, dp = c & 63;
        float acc = hyp_b[dp];
        for (int d = 0; d < 64; d++) acc += tc_b2[j * 64 + d] * hyp_w[d * 64 + dp];
        g_b2f[c] = acc;
    }
}

// ---------------- fp32 -> bf16 convert ----------------
__global__ __launch_bounds__(256) void cvt_kernel(const float* __restrict__ in,
                                                  __nv_bfloat16* __restrict__ out, int n4) {
    int i = blockIdx.x * 256 + threadIdx.x;
    if (i < n4) {
        float4 v = ((const float4*)in)[i];
        unsigned p0 = ((unsigned)__bfloat16_as_ushort(__float2bfloat16(v.y)) << 16) |
                      __bfloat16_as_ushort(__float2bfloat16(v.x));
        unsigned p1 = ((unsigned)__bfloat16_as_ushort(__float2bfloat16(v.w)) << 16) |
                      __bfloat16_as_ushort(__float2bfloat16(v.z));
        ((uint2*)out)[i] = make_uint2(p0, p1);
    }
}

// ---------------- transpose fp32 -> bf16: in[R][C] -> out[C][R] ----------------
__global__ void transpose_cvt_kernel(const float* __restrict__ in,
                                     __nv_bfloat16* __restrict__ out, int R, int C) {
    __shared__ float t[32][33];
    int cb = blockIdx.x * 32, rb = blockIdx.y * 32;
    int x = threadIdx.x, y = threadIdx.y;
#pragma unroll
    for (int i = y; i < 32; i += 8) t[i][x] = in[(size_t)(rb + i) * C + cb + x];
    __syncthreads();
#pragma unroll
    for (int i = y; i < 32; i += 8)
        out[(size_t)(cb + i) * R + rb + x] = __float2bfloat16(t[x][i]);
}

// ---------------- single-pass bf16 mma.sync GEMM -----------------------------
// C[M,N] = A[M,K](bf16) @ B[N,K]^T(bf16) + bias
// EPI=0: relu -> bf16 store;  EPI=1: expmap0 -> fp32 store
// SMEM stage = A tile (128x64 bf16, 16KB) + B tile (128x64, 16KB) = 32KB, 3 stages.
// Atom-major layout: 16B unit idx = rg*64 + seg*8 + rin  (rg=row>>3, seg=k16B, rin=row&7)
#define STG 32768

template <int EPI>
__global__ __launch_bounds__(256, 2) void gemm_bf16_kernel(
    const __nv_bfloat16* __restrict__ A, const __nv_bfloat16* __restrict__ B,
    const float* __restrict__ bias, float* __restrict__ Cf,
    __nv_bfloat16* __restrict__ Cb, int M, int N, int K) {
    extern __shared__ char dsm[];
    __shared__ float sbias[128];

    const int tid = threadIdx.x;
    const int wid = tid >> 5, lane = tid & 31;
    const int wm = wid >> 2;       // 0..1 (64 rows)
    const int wn = wid & 3;        // 0..3 (32 cols)
    const int n0 = blockIdx.x * 128;
    const int m0 = blockIdx.y * 128;
    const uint32_t sb = smem_u32(dsm);

    if (tid < 128) sbias[tid] = bias[n0 + tid];

    const int g = lane >> 3, rin = lane & 7;
    const uint32_t laneA = (uint32_t)((g & 1) * 1024 + (g >> 1) * 128 + rin * 16);
    const uint32_t laneB = (uint32_t)((g >> 1) * 1024 + (g & 1) * 128 + rin * 16);

    float acc[4][4][4];
#pragma unroll
    for (int i = 0; i < 4; i++)
#pragma unroll
        for (int n = 0; n < 4; n++)
#pragma unroll
            for (int r = 0; r < 4; r++) acc[i][n][r] = 0.f;

    const int nchunk = K >> 6;

    auto load_stage = [&](int buf, int kc) {
        const uint32_t sbase = sb + buf * STG;
#pragma unroll
        for (int it = 0; it < 8; it++) {
            int uid = tid + it * 256;      // 0..2047
            int tile = uid >> 10;          // 0:A 1:B
            int u = uid & 1023;
            int rg = u >> 6, seg = (u >> 3) & 7, rr = u & 7;
            int lrow = rg * 8 + rr;
            const __nv_bfloat16* src = tile ? B : A;
            int grow = (tile ? n0 : m0) + lrow;
            cpa16(sbase + tile * 16384 + u * 16,
                  src + (size_t)grow * K + kc * 64 + seg * 8);
        }
        CP_COMMIT();
    };

    load_stage(0, 0);
    if (nchunk > 1) load_stage(1, 1); else CP_COMMIT();

    int buf = 0;
    for (int kc = 0; kc < nchunk; kc++) {
        asm volatile("cp.async.wait_group 1;" ::: "memory");
        __syncthreads();

        const uint32_t tA = sb + buf * STG + (uint32_t)wm * 8192;
        const uint32_t tB = sb + buf * STG + 16384 + (uint32_t)wn * 4096;

#pragma unroll
        for (int j = 0; j < 4; j++) {
            uint32_t a[16], b[8];
            const uint32_t jo = (uint32_t)j * 256;
#pragma unroll
            for (int i = 0; i < 4; i++)
                LDSM4(a[4 * i], a[4 * i + 1], a[4 * i + 2], a[4 * i + 3],
                      tA + (uint32_t)i * 2048 + jo + laneA);
#pragma unroll
            for (int p = 0; p < 2; p++)
                LDSM4(b[4 * p], b[4 * p + 1], b[4 * p + 2], b[4 * p + 3],
                      tB + (uint32_t)p * 2048 + jo + laneB);
#pragma unroll
            for (int i = 0; i < 4; i++)
#pragma unroll
                for (int n = 0; n < 4; n++)
                    MMA16816(acc[i][n], a[4 * i], a[4 * i + 1], a[4 * i + 2], a[4 * i + 3],
                             b[(n >> 1) * 4 + (n & 1) * 2], b[(n >> 1) * 4 + (n & 1) * 2 + 1]);
        }
        // prefetch stage kc+2 (writes a buffer nobody is reading this iteration)
        if (kc + 2 < nchunk) load_stage((buf + 2) % 3, kc + 2);
        else CP_COMMIT();
        buf = (buf + 1) % 3;
        __syncthreads();
    }
    asm volatile("cp.async.wait_group 0;" ::: "memory");
    __syncthreads();

    // ---------------- epilogue ----------------
    if (EPI == 0) {
        __nv_bfloat16* sh = (__nv_bfloat16*)dsm;   // [128][128] bf16 = 32KB
#pragma unroll
        for (int i = 0; i < 4; i++) {
            const int r0 = 64 * wm + 16 * i + (lane >> 2);
#pragma unroll
            for (int n = 0; n < 4; n++) {
                const int col = 32 * wn + 8 * n + (lane & 3) * 2;
#pragma unroll
                for (int half = 0; half < 2; half++) {
                    const int rr = r0 + half * 8;
                    float v0 = fmaxf(acc[i][n][2 * half] + sbias[col], 0.f);
                    float v1 = fmaxf(acc[i][n][2 * half + 1] + sbias[col + 1], 0.f);
                    *(uint32_t*)(sh + rr * 128 + col) =
                        ((uint32_t)__bfloat16_as_ushort(__float2bfloat16(v1)) << 16) |
                        __bfloat16_as_ushort(__float2bfloat16(v0));
                }
            }
        }
        __syncthreads();
#pragma unroll
        for (int it = 0; it < 4; it++) {
            int idx = tid + it * 256;          // 1024 uint4
            int row = idx >> 3, seg = idx & 7;
            uint4 vh = ((const uint4*)dsm)[idx];
            *(uint4*)(Cb + (size_t)(m0 + row) * N + n0 + seg * 8) = vh;
        }
    } else {
        float* stf = (float*)dsm;              // [128][130] fp32 = 66.5KB
#pragma unroll
        for (int i = 0; i < 4; i++) {
            const int r0 = 64 * wm + 16 * i + (lane >> 2);
#pragma unroll
            for (int n = 0; n < 4; n++) {
                const int col = 32 * wn + 8 * n + (lane & 3) * 2;
#pragma unroll
                for (int half = 0; half < 2; half++) {
                    const int rr = r0 + half * 8;
                    stf[rr * 130 + col] = acc[i][n][2 * half] + sbias[col];
                    stf[rr * 130 + col + 1] = acc[i][n][2 * half + 1] + sbias[col + 1];
                }
            }
        }
        __syncthreads();
        const int row = tid >> 1, grp = tid & 1;
        const float* src = stf + row * 130 + grp * 64;
        float v[64];
        float sum = 0.f;
#pragma unroll
        for (int q = 0; q < 32; q++) {
            float2 p = *(const float2*)(src + 2 * q);
            v[2 * q] = p.x;
            v[2 * q + 1] = p.y;
            sum += p.x * p.x + p.y * p.y;
        }
        float nrm = sqrtf(fmaxf(sum, EPS_));
        float s = tanhf(nrm) / nrm;
        float* dst = Cf + (size_t)(m0 + row) * N + n0 + grp * 64;
#pragma unroll
        for (int q = 0; q < 16; q++)
            *(float4*)(dst + 4 * q) = make_float4(v[4 * q] * s, v[4 * q + 1] * s,
                                                  v[4 * q + 2] * s, v[4 * q + 3] * s);
    }
}

// ---------------- hyperbolic path search: one CTA per (b, head) -------------
__global__ __launch_bounds__(256) void attn_kernel(const float* __restrict__ label,
                                                   const int* __restrict__ y,
                                                   const int* __restrict__ mask_text) {
    __shared__ __align__(16) float q_s[64];
    __shared__ float sq_q_s, fac_s;
    __shared__ float wm[8], wd[8];
    __shared__ __align__(16) float wacc[8][64];
    __shared__ int msk[1024];

    const int bh = blockIdx.x;
    const int b = bh >> 4;
    const int hh = bh & 15;
    const int tid = threadIdx.x;
    const int w = tid >> 5;
    const int lane = tid & 31;

    if (tid < 64) q_s[tid] = label[(size_t)y[b] * 64 + tid];
    for (int i = tid; i < 1024; i += 256) msk[i] = mask_text[b * 1024 + i];
    __syncthreads();
    if (w == 0) {
        float2 qv = *(float2*)(q_s + lane * 2);
        float p = qv.x * qv.x + qv.y * qv.y;
#pragma unroll
        for (int off = 16; off; off >>= 1) p += __shfl_xor_sync(0xffffffffu, p, off);
        if (lane == 0) sq_q_s = p;
    }
    __syncthreads();

    const float* ekb = g_ek + ((size_t)b * 1024 + hh * 64) * 1024;

    for (int layer = 0; layer < 4; layer++) {
        const float sqq = sq_q_s;
        const float aq = 1.f + sqq;
        const float idq = 1.f / fmaxf(1.f - sqq, EPS_);
        const float q0 = q_s[2 * lane], q1 = q_s[2 * lane + 1];

        float m = -INFINITY, den = 0.f, a0 = 0.f, a1 = 0.f;
        for (int t = 0; t < 128; t++) {
            const int idx = w * 128 + t;
            const float2 ev =
                *(const float2*)(ekb + (size_t)(idx >> 4) * 1024 + (idx & 15) * 64 + lane * 2);
            float pd = q0 * ev.x + q1 * ev.y;
            float ps = ev.x * ev.x + ev.y * ev.y;
#pragma unroll
            for (int off = 16; off; off >>= 1) {
                pd += __shfl_xor_sync(0xffffffffu, pd, off);
                ps += __shfl_xor_sync(0xffffffffu, ps, off);
            }
            const float idk = 1.f / fmaxf(1.f - ps, EPS_);
            const float x = (aq * (1.f + ps) - 4.f * pd) * idq * idk;
            const float tt = fmaxf(x - 1.f, 1e-6f);
            float score = -log1pf(tt + sqrtf(tt * (tt + 2.f)));
            if (!msk[idx]) score = -1e9f;
            const float nm = fmaxf(m, score);
            const float sc = __expf(m - nm);
            const float wg = __expf(score - nm);
            const float cw = wg * (1.f + ps) * idk;
            const float cn = 2.f * wg * idk;
            den = den * sc + cw;
            a0 = a0 * sc + cn * ev.x;
            a1 = a1 * sc + cn * ev.y;
            m = nm;
        }
        wacc[w][2 * lane] = a0;
        wacc[w][2 * lane + 1] = a1;
        if (lane == 0) { wm[w] = m; wd[w] = den; }
        __syncthreads();

        if (tid < 64) {
            float M = wm[0];
#pragma unroll
            for (int ww = 1; ww < 8; ww++) M = fmaxf(M, wm[ww]);
            float num = 0.f, D = 0.f;
#pragma unroll
            for (int ww = 0; ww < 8; ww++) {
                float al = __expf(wm[ww] - M);
                num += al * wacc[ww][tid];
                D += al * wd[ww];
            }
            q_s[tid] = num / D;
        }
        __syncthreads();
        if (w == 0) {
            float2 mv = *(float2*)(q_s + lane * 2);
            float p = mv.x * mv.x + mv.y * mv.y;
#pragma unroll
            for (int off = 16; off; off >>= 1) p += __shfl_xor_sync(0xffffffffu, p, off);
            if (lane == 0) {
                float r = 1.f / (1.f + sqrtf(fmaxf(1.f - p, EPS_)));
                fac_s = r;
                sq_q_s = p * r * r;
            }
        }
        __syncthreads();
        if (tid < 64) q_s[tid] *= fac_s;
        __syncthreads();
    }
    if (tid < 64) g_qv[(size_t)bh * 64 + tid] = q_s[tid];
    if (tid == 0) g_sqq[bh] = sq_q_s;
}

// ---------------- label distances + aggregator MLP --------------------------
__global__ __launch_bounds__(128) void label_mlp_kernel(
    const float* __restrict__ label,
    const float* __restrict__ w1, const float* __restrict__ b1,
    const float* __restrict__ w2, const float* __restrict__ b2,
    const float* __restrict__ w3, const float* __restrict__ b3,
    const float* __restrict__ w4, const float* __restrict__ b4,
    const int* __restrict__ mask_label, float* __restrict__ out) {
    __shared__ float lab[128][65];
    __shared__ float qs[16 * 64];
    __shared__ float P[16], Qc[16];
    __shared__ float sw1[512], sb1[32], sw2[1024], sb2[32], sw3[512], sb3[16], sw4[16], sb4s[1];

    const int b = blockIdx.y;
    const int base = blockIdx.x * 128;
    const int tid = threadIdx.x;

    for (int i = tid; i < 128 * 64; i += 128) lab[i >> 6][i & 63] = label[(size_t)base * 64 + i];
    for (int i = tid; i < 1024; i += 128) qs[i] = g_qv[(size_t)b * 1024 + i];
    if (tid < 16) {
        float s = g_sqq[b * 16 + tid];
        float inv = 1.f / fmaxf(1.f - s, EPS_);
        P[tid] = (1.f + s) * inv;
        Qc[tid] = 4.f * inv;
    }
    for (int i = tid; i < 512; i += 128) sw1[i] = w1[i];
    for (int i = tid; i < 1024; i += 128) sw2[i] = w2[i];
    for (int i = tid; i < 512; i += 128) sw3[i] = w3[i];
    if (tid < 32) { sb1[tid] = b1[tid]; sb2[tid] = b2[tid]; }
    if (tid < 16) { sb3[tid] = b3[tid]; sw4[tid] = w4[tid]; }
    if (tid == 0) sb4s[0] = b4[0];
    __syncthreads();

    float sq_l = 0.f;
#pragma unroll 8
    for (int d = 0; d < 64; d++) { float v = lab[tid][d]; sq_l += v * v; }
    const float invl = 1.f / fmaxf(1.f - sq_l, EPS_);
    const float L1 = (1.f + sq_l) * invl;

    float dh[16];
#pragma unroll
    for (int h = 0; h < 16; h++) {
        float dot = 0.f;
#pragma unroll 8
        for (int d = 0; d < 64; d++) dot += qs[h * 64 + d] * lab[tid][d];
        float x = P[h] * L1 - Qc[h] * invl * dot;
        float tt = fmaxf(x - 1.f, 1e-6f);
        dh[h] = log1pf(tt + sqrtf(tt * (tt + 2.f)));
    }
    float x1[32];
#pragma unroll
    for (int j = 0; j < 32; j++) {
        float a = sb1[j];
#pragma unroll
        for (int h = 0; h < 16; h++) a += dh[h] * sw1[h * 32 + j];
        x1[j] = fmaxf(a, 0.f);
    }
    float x2[32];
#pragma unroll
    for (int j = 0; j < 32; j++) {
        float a = sb2[j];
#pragma unroll
        for (int i = 0; i < 32; i++) a += x1[i] * sw2[i * 32 + j];
        x2[j] = fmaxf(a, 0.f);
    }
    float x3[16];
#pragma unroll
    for (int j = 0; j < 16; j++) {
        float a = sb3[j];
#pragma unroll
        for (int i = 0; i < 32; i++) a += x2[i] * sw3[i * 16 + j];
        x3[j] = fmaxf(a, 0.f);
    }
    float val = sb4s[0];
#pragma unroll
    for (int h = 0; h < 16; h++) val += x3[h] * sw4[h];

    const int n = base + tid;
    out[(size_t)b * NLABEL + n] = (mask_label[(size_t)b * NLABEL + n] > 0) ? val : -500.f;
}

// ---------------- launch -----------------------------------------------------
extern "C" void kernel_launch(void* const* d_in, const int* in_sizes, int n_in,
                              void* d_out, int out_size) {
    const float* e = (const float*)d_in[0];
    const float* label = (const float*)d_in[1];
    const float* tc_w1 = (const float*)d_in[2];
    const float* tc_b1 = (const float*)d_in[3];
    const float* tc_w2 = (const float*)d_in[4];
    const float* tc_b2 = (const float*)d_in[5];
    const float* hyp_w = (const float*)d_in[6];
    const float* hyp_b = (const float*)d_in[7];
    const float* aw1 = (const float*)d_in[8];
    const float* ab1 = (const float*)d_in[9];
    const float* aw2 = (const float*)d_in[10];
    const float* ab2 = (const float*)d_in[11];
    const float* aw3 = (const float*)d_in[12];
    const float* ab3 = (const float*)d_in[13];
    const float* aw4 = (const float*)d_in[14];
    const float* ab4 = (const float*)d_in[15];
    const int* y = (const int*)d_in[16];
    const int* mt = (const int*)d_in[17];
    const int* ml = (const int*)d_in[18];
    float* out = (float*)d_out;

    __nv_bfloat16 *e16, *h1, *w1t, *w2t;
    float *ekp, *w2fp, *b2fp;
    cudaGetSymbolAddress((void**)&e16, g_e16);
    cudaGetSymbolAddress((void**)&h1, g_h1);
    cudaGetSymbolAddress((void**)&w1t, g_w1t);
    cudaGetSymbolAddress((void**)&w2t, g_w2t);
    cudaGetSymbolAddress((void**)&ekp, g_ek);
    cudaGetSymbolAddress((void**)&w2fp, g_w2f);
    cudaGetSymbolAddress((void**)&b2fp, g_b2f);

    const int smem_bytes = 3 * STG;   // 96KB (>= 66.5KB epilogue staging)
    cudaFuncSetAttribute(gemm_bf16_kernel<0>, cudaFuncAttributeMaxDynamicSharedMemorySize,
                         smem_bytes);
    cudaFuncSetAttribute(gemm_bf16_kernel<1>, cudaFuncAttributeMaxDynamicSharedMemorySize,
                         smem_bytes);

    // prep
    fold_w2_kernel<<<2048, 256>>>(tc_w2, hyp_w);
    fold_b2_kernel<<<4, 256>>>(tc_b2, hyp_w, hyp_b);
    transpose_cvt_kernel<<<dim3(2048 / 32, 1024 / 32), dim3(32, 8)>>>(tc_w1, w1t, 1024, 2048);
    transpose_cvt_kernel<<<dim3(1024 / 32, 2048 / 32), dim3(32, 8)>>>(w2fp, w2t, 2048, 1024);
    cvt_kernel<<<(MROWS * 1024 / 4 + 255) / 256, 256>>>(e, e16, MROWS * 1024 / 4);

    // GEMM1: h1 = relu(e @ w1 + b1) -> bf16
    gemm_bf16_kernel<0><<<dim3(16, 256), 256, smem_bytes>>>(
        e16, w1t, tc_b1, nullptr, h1, MROWS, 2048, 1024);
    // GEMM2: ek = expmap0(h1 @ w2f + b2f) -> fp32
    gemm_bf16_kernel<1><<<dim3(8, 256), 256, smem_bytes>>>(
        h1, w2t, b2fp, ekp, nullptr, MROWS, 1024, 2048);

    attn_kernel<<<512, 256>>>(label, y, mt);
    label_mlp_kernel<<<dim3(NLABEL / 128, BBATCH), 128>>>(label, aw1, ab1, aw2, ab2,
                                                          aw3, ab3, aw4, ab4, ml, out);
}